// round 1
// baseline (speedup 1.0000x reference)
#include <cuda_runtime.h>
#include <cstdint>

// Problem constants (fixed shapes)
#define T_DIM 64
#define U_DIM 142
#define I_DIM 4500
#define K_TOP 10

#define NEG_BIG (-3.0e38f)

__global__ __launch_bounds__(256, 8)
void ucf_kernel(const float* __restrict__ qos,        // [T, U, I]
                const float* __restrict__ user_avg,   // [T, U]
                const float* __restrict__ user_sim,   // [U, U]
                const int*   __restrict__ user_id,    // [B]
                const int*   __restrict__ item_id,    // [B]
                const int*   __restrict__ time_id,    // [B]
                float*       __restrict__ out,        // [B]
                int B)
{
    const int warp = (blockIdx.x * blockDim.x + threadIdx.x) >> 5;
    const int lane = threadIdx.x & 31;
    if (warp >= B) return;

    const int u = user_id[warp];
    const int i = item_id[warp];
    const int t = time_id[warp];

    const float* qbase = qos + (int64_t)t * (U_DIM * I_DIM) + i; // column stride I_DIM
    const float* abase = user_avg + t * U_DIM;
    const float* sbase = user_sim + u * U_DIM;

    // Per-lane slots: v = lane + 32*s, s in [0,5)
    float m0 = NEG_BIG, m1 = NEG_BIG, m2 = NEG_BIG, m3 = NEG_BIG, m4 = NEG_BIG;
    float d0 = 0.f, d1 = 0.f, d2 = 0.f, d3 = 0.f, d4 = 0.f;

    // Front-batch all scattered qos loads for MLP
    {
        int v;
        float c, s, a;
        v = lane;            // < 142 always
        c = __ldg(qbase + (int64_t)v * I_DIM); s = __ldg(sbase + v); a = __ldg(abase + v);
        m0 = (c > 0.f) ? s : 0.f; d0 = c - a;
        v = lane + 32;
        c = __ldg(qbase + (int64_t)v * I_DIM); s = __ldg(sbase + v); a = __ldg(abase + v);
        m1 = (c > 0.f) ? s : 0.f; d1 = c - a;
        v = lane + 64;
        c = __ldg(qbase + (int64_t)v * I_DIM); s = __ldg(sbase + v); a = __ldg(abase + v);
        m2 = (c > 0.f) ? s : 0.f; d2 = c - a;
        v = lane + 96;
        c = __ldg(qbase + (int64_t)v * I_DIM); s = __ldg(sbase + v); a = __ldg(abase + v);
        m3 = (c > 0.f) ? s : 0.f; d3 = c - a;
        v = lane + 128;
        if (v < U_DIM) {
            c = __ldg(qbase + (int64_t)v * I_DIM); s = __ldg(sbase + v); a = __ldg(abase + v);
            m4 = (c > 0.f) ? s : 0.f; d4 = c - a;
        }
    }

    float wsum = 0.f;   // sum of selected sim values
    float acc  = 0.f;   // sum of sim * (r_vs - avg_v)

    #pragma unroll
    for (int k = 0; k < K_TOP; ++k) {
        // local argmax over 5 slots (value-major, lower global index wins ties
        // by evaluation order: slot0 checked first = lowest v)
        float bv = m0; int bslot = 0;
        if (m1 > bv) { bv = m1; bslot = 1; }
        if (m2 > bv) { bv = m2; bslot = 2; }
        if (m3 > bv) { bv = m3; bslot = 3; }
        if (m4 > bv) { bv = m4; bslot = 4; }
        int bidx = lane + (bslot << 5);   // global user index v

        // warp argmax; tie -> smaller index (matches lax.top_k stability)
        #pragma unroll
        for (int off = 16; off > 0; off >>= 1) {
            float ov = __shfl_xor_sync(0xffffffffu, bv,   off);
            int   oi = __shfl_xor_sync(0xffffffffu, bidx, off);
            if (ov > bv || (ov == bv && oi < bidx)) { bv = ov; bidx = oi; }
        }
        // all lanes now agree on (bv, bidx)
        int wlane = bidx & 31;
        int wslot = bidx >> 5;

        // broadcast winner's d
        float dcand = (wslot == 0) ? d0 :
                      (wslot == 1) ? d1 :
                      (wslot == 2) ? d2 :
                      (wslot == 3) ? d3 : d4;
        float dwin = __shfl_sync(0xffffffffu, dcand, wlane);

        // invalidate winner
        if (lane == wlane) {
            if      (wslot == 0) m0 = NEG_BIG;
            else if (wslot == 1) m1 = NEG_BIG;
            else if (wslot == 2) m2 = NEG_BIG;
            else if (wslot == 3) m3 = NEG_BIG;
            else                 m4 = NEG_BIG;
        }

        wsum += bv;
        acc  += bv * dwin;
    }

    if (lane == 0) {
        float avg_u = __ldg(abase + u);
        out[warp] = avg_u + acc / (wsum + 1e-8f);
    }
}

extern "C" void kernel_launch(void* const* d_in, const int* in_sizes, int n_in,
                              void* d_out, int out_size)
{
    const float* qos      = (const float*)d_in[0];
    const float* user_avg = (const float*)d_in[1];
    const float* user_sim = (const float*)d_in[2];
    const int*   user_id  = (const int*)  d_in[3];
    const int*   item_id  = (const int*)  d_in[4];
    const int*   time_id  = (const int*)  d_in[5];
    float* out = (float*)d_out;

    const int B = in_sizes[3];                 // batch size from user_id length
    const int threads = 256;                   // 8 warps/block, 1 warp per row
    const int blocks  = (B * 32 + threads - 1) / threads;
    ucf_kernel<<<blocks, threads>>>(qos, user_avg, user_sim,
                                    user_id, item_id, time_id, out, B);
}